// round 2
// baseline (speedup 1.0000x reference)
#include <cuda_runtime.h>
#include <math.h>

// Problem constants (fixed shapes)
#define TOK   32      // only channel n=0 of each batch survives the final slice
#define LSEQ  1024
#define CCH   34
#define DDIM  256
#define NEXP  8
#define PTCH  4       // only first 4 patches survive flat[:, :1024]
#define PLEN  16
#define PRED  96

// Scratch (device globals — no allocation allowed)
__device__ float g_stats[TOK * 2];            // mean, std per token
__device__ float g_xp[TOK * PTCH * DDIM];     // 128 x 256
__device__ float g_gates[TOK * PTCH * NEXP];  // 128 x 8
__device__ float g_comb[TOK * LSEQ];          // 32 x 1024 (combined, pre-denorm)

// ---------------------------------------------------------------------------
// K1: per-token stats + patch projection + router gates. Also zero g_comb.
// grid = 32 (one per token/batch), block = 256
// ---------------------------------------------------------------------------
__global__ void k1_stats_xp_gates(const float* __restrict__ x,
                                  const float* __restrict__ Wp,
                                  const float* __restrict__ bp,
                                  const float* __restrict__ Wr,
                                  const float* __restrict__ br)
{
    __shared__ float row[LSEQ];
    __shared__ float xps[PTCH * DDIM];
    __shared__ float red[256];
    __shared__ float lgs[32];
    __shared__ float s_mean, s_std;

    const int b = blockIdx.x;
    const int tid = threadIdx.x;

    // row = x[b, :, 2]  (strided by C=34)
    const float* xb = x + (size_t)b * LSEQ * CCH + 2;
    for (int i = tid; i < LSEQ; i += 256) row[i] = xb[(size_t)i * CCH];
    __syncthreads();

    // mean
    float s = 0.f;
    for (int i = tid; i < LSEQ; i += 256) s += row[i];
    red[tid] = s; __syncthreads();
    #pragma unroll
    for (int o = 128; o > 0; o >>= 1) { if (tid < o) red[tid] += red[tid + o]; __syncthreads(); }
    if (tid == 0) s_mean = red[0] * (1.f / LSEQ);
    __syncthreads();
    const float mean = s_mean;

    // var about mean, std = sqrt(var + 1e-5)
    s = 0.f;
    for (int i = tid; i < LSEQ; i += 256) { float d = row[i] - mean; s += d * d; }
    red[tid] = s; __syncthreads();
    #pragma unroll
    for (int o = 128; o > 0; o >>= 1) { if (tid < o) red[tid] += red[tid + o]; __syncthreads(); }
    if (tid == 0) s_std = sqrtf(red[0] * (1.f / LSEQ) + 1e-5f);
    __syncthreads();
    const float stdv = s_std;
    if (tid == 0) { g_stats[b * 2] = mean; g_stats[b * 2 + 1] = stdv; }

    // normalize first 64 samples (4 patches x 16)
    if (tid < PTCH * PLEN) row[tid] = (row[tid] - mean) / stdv;

    // zero combine buffer for this token (K2 accumulates via atomics)
    for (int i = tid; i < LSEQ; i += 256) g_comb[b * LSEQ + i] = 0.f;
    __syncthreads();

    // xp[p][j] = patch_p . W_proj[j] + b_proj[j]; thread = j, loop p
    {
        const int j = tid;
        float wreg[PLEN];
        #pragma unroll
        for (int k = 0; k < PLEN; k++) wreg[k] = Wp[j * PLEN + k];
        const float bj = bp[j];
        #pragma unroll
        for (int p = 0; p < PTCH; p++) {
            float a = bj;
            #pragma unroll
            for (int k = 0; k < PLEN; k++) a += row[p * PLEN + k] * wreg[k];
            xps[p * DDIM + j] = a;
            g_xp[(b * PTCH + p) * DDIM + j] = a;
        }
    }
    __syncthreads();

    // router logits (32 outputs: p x e)
    if (tid < 32) {
        const int p = tid >> 3, e = tid & 7;
        float lg = br[e];
        const float* wr = Wr + e * DDIM;
        const float* xr = xps + p * DDIM;
        for (int jj = 0; jj < DDIM; jj++) lg += xr[jj] * wr[jj];
        lgs[tid] = lg;
    }
    __syncthreads();

    // softmax per patch
    if (tid < PTCH) {
        float mx = -1e30f;
        #pragma unroll
        for (int e = 0; e < NEXP; e++) mx = fmaxf(mx, lgs[tid * 8 + e]);
        float ex[NEXP]; float sm = 0.f;
        #pragma unroll
        for (int e = 0; e < NEXP; e++) { ex[e] = expf(lgs[tid * 8 + e] - mx); sm += ex[e]; }
        const float inv = 1.f / sm;
        #pragma unroll
        for (int e = 0; e < NEXP; e++) g_gates[(b * PTCH + tid) * NEXP + e] = ex[e] * inv;
    }
}

// ---------------------------------------------------------------------------
// K2: gated expert GEMM. combined[tp][h] += g[tp][e]*(xp[tp].We[e][h] + be[e][h])
// grid = 128 blocks: e (8) x h-tile (16 tiles of 16 h). All 128 tp rows per block.
// Thread tile: 4 tp x 2 h, k staged through shared in 64-wide tiles.
// ---------------------------------------------------------------------------
__global__ void k2_experts(const float* __restrict__ We,
                           const float* __restrict__ be)
{
    __shared__ float xp_s[128][68];  // stride 68 = 4 mod 32 -> conflict-free float4
    __shared__ float w_s[16][68];

    const int e  = blockIdx.x >> 4;
    const int h0 = (blockIdx.x & 15) * 16;
    const int tid = threadIdx.x, lane = tid & 31, warp = tid >> 5;

    float acc[4][2] = {};
    const float* Wbase = We + ((size_t)e * DDIM + h0) * DDIM;

    for (int kt = 0; kt < 4; kt++) {
        const int k0 = kt * 64;
        // stage xp tile: 128 rows x 64 cols (2048 float4, 8 per thread, coalesced)
        #pragma unroll
        for (int i = 0; i < 8; i++) {
            const int idx = tid + i * 256;
            const int r = idx >> 4, c = (idx & 15) * 4;
            float4 v = *(const float4*)&g_xp[r * DDIM + k0 + c];
            *(float4*)&xp_s[r][c] = v;
        }
        // stage W tile: 16 rows x 64 cols (256 float4, 1 per thread)
        {
            const int r = tid >> 4, c = (tid & 15) * 4;
            float4 v = *(const float4*)&Wbase[r * DDIM + k0 + c];
            *(float4*)&w_s[r][c] = v;
        }
        __syncthreads();

        #pragma unroll
        for (int kk = 0; kk < 64; kk += 4) {
            const float4 w0 = *(const float4*)&w_s[warp * 2 + 0][kk];
            const float4 w1 = *(const float4*)&w_s[warp * 2 + 1][kk];
            #pragma unroll
            for (int q = 0; q < 4; q++) {
                const float4 xv = *(const float4*)&xp_s[lane + 32 * q][kk];
                acc[q][0] += xv.x * w0.x + xv.y * w0.y + xv.z * w0.z + xv.w * w0.w;
                acc[q][1] += xv.x * w1.x + xv.y * w1.y + xv.z * w1.z + xv.w * w1.w;
            }
        }
        __syncthreads();
    }

    #pragma unroll
    for (int q = 0; q < 4; q++) {
        const int tp = lane + 32 * q;
        const int t = tp >> 2, p = tp & 3;
        const float g = g_gates[(t * PTCH + p) * NEXP + e];
        #pragma unroll
        for (int j = 0; j < 2; j++) {
            const int h = h0 + warp * 2 + j;
            const float val = g * (acc[q][j] + be[e * DDIM + h]);
            atomicAdd(&g_comb[t * LSEQ + p * DDIM + h], val);
        }
    }
}

// ---------------------------------------------------------------------------
// K3: denorm + head. out[b][t] = (comb[b]*std+mean) . W_head[t] + b_head[t]
// grid = 32 (b), block = 256 (8 warps, warp-per-output-row)
// ---------------------------------------------------------------------------
__global__ void k3_head(const float* __restrict__ Wh,
                        const float* __restrict__ bh,
                        float* __restrict__ out)
{
    __shared__ float tl[LSEQ];
    const int b = blockIdx.x, tid = threadIdx.x, lane = tid & 31, warp = tid >> 5;
    const float mean = g_stats[b * 2], stdv = g_stats[b * 2 + 1];

    for (int i = tid; i < LSEQ; i += 256) tl[i] = g_comb[b * LSEQ + i] * stdv + mean;
    __syncthreads();

    for (int t = warp; t < PRED; t += 8) {
        float acc = 0.f;
        const float* wrow = Wh + (size_t)t * LSEQ;
        #pragma unroll
        for (int i = 0; i < 8; i++) {
            const float4 w  = *(const float4*)&wrow[lane * 4 + i * 128];
            const float4 xv = *(const float4*)&tl[lane * 4 + i * 128];
            acc += w.x * xv.x + w.y * xv.y + w.z * xv.z + w.w * xv.w;
        }
        #pragma unroll
        for (int o = 16; o > 0; o >>= 1) acc += __shfl_down_sync(0xffffffffu, acc, o);
        if (lane == 0) out[b * PRED + t] = acc + bh[t];
    }
}

// ---------------------------------------------------------------------------
extern "C" void kernel_launch(void* const* d_in, const int* in_sizes, int n_in,
                              void* d_out, int out_size)
{
    const float* x  = (const float*)d_in[0];
    // d_in[1..3]: x_mark_enc, x_dec, x_mark_dec — unused by the reference math
    const float* Wp = (const float*)d_in[4];
    const float* bp = (const float*)d_in[5];
    const float* Wr = (const float*)d_in[6];
    const float* br = (const float*)d_in[7];
    const float* We = (const float*)d_in[8];
    const float* be = (const float*)d_in[9];
    const float* Wh = (const float*)d_in[10];
    const float* bh = (const float*)d_in[11];
    float* out = (float*)d_out;

    k1_stats_xp_gates<<<32, 256>>>(x, Wp, bp, Wr, br);
    k2_experts<<<128, 256>>>(We, be);
    k3_head<<<32, 256>>>(Wh, bh, out);
}

// round 5
// speedup vs baseline: 1.0009x; 1.0009x over previous
#include <cuda_runtime.h>
#include <math.h>

// Problem constants (fixed shapes)
#define TOK   32      // only channel n=0 of each batch survives the final slice
#define LSEQ  1024
#define CCH   34
#define DDIM  256
#define NEXP  8
#define PTCH  4       // only first 4 patches survive flat[:, :1024]
#define PLEN  16
#define PRED  96

// Scratch (device globals — no allocation allowed)
__device__ float  g_stats[TOK * 2];            // mean, std per token
__device__ float2 g_part[TOK * 4];             // per-quarter (sum, sumsq)
__device__ float  g_row64[TOK * 64];           // first 64 raw samples per token
__device__ float  g_xp[TOK * PTCH * DDIM];     // 128 x 256
__device__ float  g_gates[TOK * PTCH * NEXP];  // 128 x 8
__device__ float  g_comb[TOK * LSEQ];          // 32 x 1024 (combined, pre-denorm)

// ---------------------------------------------------------------------------
// K0: wide gather of x[b, :, 2] + partial stats + zero g_comb.
// grid = 128 (b x quarter), block = 256. Spreads the strided DRAM gather
// across the whole chip so latency is covered by MLP.
// ---------------------------------------------------------------------------
__global__ void k0_gather(const float* __restrict__ x)
{
    __shared__ float2 wsum[8];
    const int b = blockIdx.x >> 2, q = blockIdx.x & 3;
    const int tid = threadIdx.x, lane = tid & 31, warp = tid >> 5;
    const int i = q * 256 + tid;

    const float v = x[((size_t)b * LSEQ + i) * CCH + 2];
    g_comb[b * LSEQ + i] = 0.f;
    if (q == 0 && tid < 64) g_row64[b * 64 + tid] = v;

    float s = v, s2 = v * v;
    #pragma unroll
    for (int o = 16; o > 0; o >>= 1) {
        s  += __shfl_down_sync(0xffffffffu, s,  o);
        s2 += __shfl_down_sync(0xffffffffu, s2, o);
    }
    if (lane == 0) wsum[warp] = make_float2(s, s2);
    __syncthreads();
    if (tid == 0) {
        float a = 0.f, a2 = 0.f;
        #pragma unroll
        for (int w = 0; w < 8; w++) { a += wsum[w].x; a2 += wsum[w].y; }
        g_part[b * 4 + q] = make_float2(a, a2);
    }
}

// ---------------------------------------------------------------------------
// K1: finalize stats + patch projection + router gates.
// grid = 32, block = 256. All inputs now contiguous in scratch.
// ---------------------------------------------------------------------------
__global__ void k1_xp_gates(const float* __restrict__ Wp,
                            const float* __restrict__ bp,
                            const float* __restrict__ Wr,
                            const float* __restrict__ br)
{
    __shared__ float xn[64];
    __shared__ float xps[PTCH * DDIM];
    __shared__ float lgs[32];
    __shared__ float s_mean, s_std;

    const int b = blockIdx.x, tid = threadIdx.x;

    if (tid == 0) {
        float s = 0.f, s2 = 0.f;
        #pragma unroll
        for (int q = 0; q < 4; q++) { float2 p = g_part[b * 4 + q]; s += p.x; s2 += p.y; }
        const float mean = s * (1.f / LSEQ);
        // var = E[x^2] - mean^2  (stable enough here; x ~ N(0,1))
        const float var = s2 * (1.f / LSEQ) - mean * mean;
        const float stdv = sqrtf(var + 1e-5f);
        s_mean = mean; s_std = stdv;
        g_stats[b * 2] = mean; g_stats[b * 2 + 1] = stdv;
    }
    __syncthreads();
    const float mean = s_mean, inv_std = 1.f / s_std;

    if (tid < 64) xn[tid] = (g_row64[b * 64 + tid] - mean) * inv_std;
    __syncthreads();

    // xp[p][j] = patch_p . W_proj[j] + b_proj[j]; thread = j, loop p
    {
        const int j = tid;
        float wreg[PLEN];
        #pragma unroll
        for (int k = 0; k < PLEN; k++) wreg[k] = Wp[j * PLEN + k];
        const float bj = bp[j];
        #pragma unroll
        for (int p = 0; p < PTCH; p++) {
            float a = bj;
            #pragma unroll
            for (int k = 0; k < PLEN; k++) a += xn[p * PLEN + k] * wreg[k];
            xps[p * DDIM + j] = a;
            g_xp[(b * PTCH + p) * DDIM + j] = a;
        }
    }
    __syncthreads();

    // router logits (32 outputs: p x e)
    if (tid < 32) {
        const int p = tid >> 3, e = tid & 7;
        float lg = br[e];
        const float* wr = Wr + e * DDIM;
        const float* xr = xps + p * DDIM;
        #pragma unroll 8
        for (int jj = 0; jj < DDIM; jj++) lg += xr[jj] * wr[jj];
        lgs[tid] = lg;
    }
    __syncthreads();

    // softmax per patch
    if (tid < PTCH) {
        float mx = -1e30f;
        #pragma unroll
        for (int e = 0; e < NEXP; e++) mx = fmaxf(mx, lgs[tid * 8 + e]);
        float ex[NEXP]; float sm = 0.f;
        #pragma unroll
        for (int e = 0; e < NEXP; e++) { ex[e] = expf(lgs[tid * 8 + e] - mx); sm += ex[e]; }
        const float inv = 1.f / sm;
        #pragma unroll
        for (int e = 0; e < NEXP; e++) g_gates[(b * PTCH + tid) * NEXP + e] = ex[e] * inv;
    }
}

// ---------------------------------------------------------------------------
// K2: gated expert GEMM with packed fma.rn.f32x2 (2 MACs/inst) and 4 h per
// thread (halves shared-load traffic vs 2 h).
// grid = 128: e (8) x h-tile (16 tiles of 16 h). block = 256 (8 warps).
// Warp w: tp rows (w>>2)*64 + q*32 + lane (q=0,1); h = h0 + (w&3)*4 + hh.
// ---------------------------------------------------------------------------
__device__ __forceinline__ void ffma2(unsigned long long& acc,
                                      unsigned long long a,
                                      unsigned long long b)
{
    asm("fma.rn.f32x2 %0, %1, %2, %0;" : "+l"(acc) : "l"(a), "l"(b));
}

__global__ void k2_experts(const float* __restrict__ We,
                           const float* __restrict__ be)
{
    __shared__ float xp_s[128][68];  // stride 68 = 4 mod 32 -> conflict-free 16B LDS
    __shared__ float w_s[16][68];

    const int e  = blockIdx.x >> 4;
    const int h0 = (blockIdx.x & 15) * 16;
    const int tid = threadIdx.x, lane = tid & 31, warp = tid >> 5;
    const int row_base = (warp >> 2) * 64;     // 0 or 64
    const int hl = (warp & 3) * 4;             // local h base: 0,4,8,12

    unsigned long long acc[2][4];
    #pragma unroll
    for (int q = 0; q < 2; q++)
        #pragma unroll
        for (int j = 0; j < 4; j++) acc[q][j] = 0ull;

    const float* Wbase = We + ((size_t)e * DDIM + h0) * DDIM;

    for (int kt = 0; kt < 4; kt++) {
        const int k0 = kt * 64;
        // stage xp tile: 128 rows x 64 cols (2048 float4, 8 per thread)
        #pragma unroll
        for (int i = 0; i < 8; i++) {
            const int idx = tid + i * 256;
            const int r = idx >> 4, c = (idx & 15) * 4;
            *(float4*)&xp_s[r][c] = *(const float4*)&g_xp[r * DDIM + k0 + c];
        }
        // stage W tile: 16 rows x 64 cols (256 float4, 1 per thread)
        {
            const int r = tid >> 4, c = (tid & 15) * 4;
            *(float4*)&w_s[r][c] = *(const float4*)&Wbase[r * DDIM + k0 + c];
        }
        __syncthreads();

        #pragma unroll
        for (int kk = 0; kk < 64; kk += 4) {
            ulonglong2 xv[2];
            #pragma unroll
            for (int q = 0; q < 2; q++)
                xv[q] = *(const ulonglong2*)&xp_s[row_base + q * 32 + lane][kk];
            #pragma unroll
            for (int j = 0; j < 4; j++) {
                const ulonglong2 wv = *(const ulonglong2*)&w_s[hl + j][kk];
                #pragma unroll
                for (int q = 0; q < 2; q++) {
                    ffma2(acc[q][j], xv[q].x, wv.x);
                    ffma2(acc[q][j], xv[q].y, wv.y);
                }
            }
        }
        __syncthreads();
    }

    #pragma unroll
    for (int q = 0; q < 2; q++) {
        const int tp = row_base + q * 32 + lane;
        const int t = tp >> 2, p = tp & 3;
        const float g = g_gates[(t * PTCH + p) * NEXP + e];
        #pragma unroll
        for (int j = 0; j < 4; j++) {
            const int h = h0 + hl + j;
            const float2 f = *(const float2*)&acc[q][j];
            const float val = g * (f.x + f.y + be[e * DDIM + h]);
            atomicAdd(&g_comb[t * LSEQ + p * DDIM + h], val);
        }
    }
}

// ---------------------------------------------------------------------------
// K3: denorm + head. out[b][t] = (comb[b]*std+mean) . W_head[t] + b_head[t]
// grid = 32 (b), block = 256 (8 warps, warp-per-output-row)
// ---------------------------------------------------------------------------
__global__ void k3_head(const float* __restrict__ Wh,
                        const float* __restrict__ bh,
                        float* __restrict__ out)
{
    __shared__ float tl[LSEQ];
    const int b = blockIdx.x, tid = threadIdx.x, lane = tid & 31, warp = tid >> 5;
    const float mean = g_stats[b * 2], stdv = g_stats[b * 2 + 1];

    for (int i = tid; i < LSEQ; i += 256) tl[i] = g_comb[b * LSEQ + i] * stdv + mean;
    __syncthreads();

    for (int t = warp; t < PRED; t += 8) {
        float acc = 0.f;
        const float* wrow = Wh + (size_t)t * LSEQ;
        #pragma unroll
        for (int i = 0; i < 8; i++) {
            const float4 w  = *(const float4*)&wrow[lane * 4 + i * 128];
            const float4 xv = *(const float4*)&tl[lane * 4 + i * 128];
            acc += w.x * xv.x + w.y * xv.y + w.z * xv.z + w.w * xv.w;
        }
        #pragma unroll
        for (int o = 16; o > 0; o >>= 1) acc += __shfl_down_sync(0xffffffffu, acc, o);
        if (lane == 0) out[b * PRED + t] = acc + bh[t];
    }
}

// ---------------------------------------------------------------------------
extern "C" void kernel_launch(void* const* d_in, const int* in_sizes, int n_in,
                              void* d_out, int out_size)
{
    const float* x  = (const float*)d_in[0];
    // d_in[1..3]: x_mark_enc, x_dec, x_mark_dec — unused by the reference math
    const float* Wp = (const float*)d_in[4];
    const float* bp = (const float*)d_in[5];
    const float* Wr = (const float*)d_in[6];
    const float* br = (const float*)d_in[7];
    const float* We = (const float*)d_in[8];
    const float* be = (const float*)d_in[9];
    const float* Wh = (const float*)d_in[10];
    const float* bh = (const float*)d_in[11];
    float* out = (float*)d_out;

    k0_gather<<<128, 256>>>(x);
    k1_xp_gates<<<32, 256>>>(Wp, bp, Wr, br);
    k2_experts<<<128, 256>>>(We, be);
    k3_head<<<32, 256>>>(Wh, bh, out);
}

// round 8
// speedup vs baseline: 1.1872x; 1.1862x over previous
#include <cuda_runtime.h>
#include <math.h>

// Problem constants (fixed shapes)
#define TOK   32      // only channel n=0 of each batch survives the final slice
#define LSEQ  1024
#define CCH   34
#define DDIM  256
#define NEXP  8
#define PTCH  4       // only first 4 patches survive flat[:, :1024]
#define PLEN  16
#define PRED  96
#define GRID  128
#define NTHR  256

// Scratch (device globals — no allocation allowed)
__device__ float  g_stats[TOK * 2];              // mean, std per token
__device__ float2 g_part[TOK * 4];               // per-quarter (sum, sumsq)
__device__ float  g_row64[TOK * 64];             // first 64 raw samples per token
__device__ float  g_xp[TOK * PTCH * DDIM];       // 128 x 256
__device__ float  g_gates[TOK * PTCH * NEXP];    // 128 x 8
__device__ float  g_epart[NEXP][TOK * PTCH][DDIM]; // per-expert gated partials (1 MB)
__device__ unsigned g_cnt[4];                    // barrier arrive counters (reset each use)
__device__ unsigned g_gen[4];                    // barrier generations (monotonic)

// ---------------------------------------------------------------------------
// Grid barrier: all GRID CTAs co-resident (grid <= SM count), sense via gen.
// Counter self-resets so graph replays of the same kernel stay correct.
// ---------------------------------------------------------------------------
__device__ __forceinline__ void grid_barrier(int k)
{
    __syncthreads();
    __threadfence();                       // all threads: publish prior writes
    if (threadIdx.x == 0) {
        volatile unsigned* genp = &g_gen[k];
        const unsigned g = *genp;
        const unsigned arrived = atomicAdd(&g_cnt[k], 1u) + 1u;
        if (arrived == GRID) {
            g_cnt[k] = 0;
            __threadfence();
            atomicAdd(&g_gen[k], 1u);      // release
        } else {
            while (*genp == g) { __nanosleep(128); }
        }
        __threadfence();                   // acquire
    }
    __syncthreads();
}

__device__ __forceinline__ void ffma2(unsigned long long& acc,
                                      unsigned long long a,
                                      unsigned long long b)
{
    asm("fma.rn.f32x2 %0, %1, %2, %0;" : "+l"(acc) : "l"(a), "l"(b));
}

// Shared memory, phase-overlaid (max ~39.2 KB < 48 KB static limit)
struct SmemA { float2 wsum[8]; };
struct SmemB { float xn[64]; float xps[PTCH * DDIM]; float lgs[32]; float mean, stdv; };
struct SmemC { float xp[128][68]; float w[16][68]; };  // stride 68: conflict-free 16B LDS
struct SmemD { float comb[LSEQ]; };

__global__ void __launch_bounds__(NTHR, 1)
fused_kernel(const float* __restrict__ x,
             const float* __restrict__ Wp, const float* __restrict__ bp,
             const float* __restrict__ Wr, const float* __restrict__ br,
             const float* __restrict__ We, const float* __restrict__ be,
             const float* __restrict__ Wh, const float* __restrict__ bh,
             float* __restrict__ out)
{
    __shared__ union { SmemA a; SmemB b; SmemC c; SmemD d; } sm;

    const int bid = blockIdx.x;
    const int tid = threadIdx.x, lane = tid & 31, warp = tid >> 5;

    // ---- L2 prefetch of weights used in later phases (overlaps phase A) ----
    {
        // We: 2MB / 128 CTAs = 16KB = 128 lines of 128B
        const char* wp = (const char*)(We + (size_t)bid * 4096);
        if (tid < 128)
            asm volatile("prefetch.global.L2 [%0];" :: "l"(wp + tid * 128));
        // Wh: 384KB / 128 CTAs = 3KB = 24 lines
        const char* hp = (const char*)(Wh + (size_t)bid * 768);
        if (tid < 24)
            asm volatile("prefetch.global.L2 [%0];" :: "l"(hp + tid * 128));
    }

    // =========================== Phase A: gather + stats ====================
    {
        const int b = bid >> 2, q = bid & 3;
        const int i = q * 256 + tid;
        const float v = x[((size_t)b * LSEQ + i) * CCH + 2];
        if (q == 0 && tid < 64) g_row64[b * 64 + tid] = v;

        float s = v, s2 = v * v;
        #pragma unroll
        for (int o = 16; o > 0; o >>= 1) {
            s  += __shfl_down_sync(0xffffffffu, s,  o);
            s2 += __shfl_down_sync(0xffffffffu, s2, o);
        }
        if (lane == 0) sm.a.wsum[warp] = make_float2(s, s2);
        __syncthreads();
        if (tid == 0) {
            float a = 0.f, a2 = 0.f;
            #pragma unroll
            for (int w = 0; w < 8; w++) { a += sm.a.wsum[w].x; a2 += sm.a.wsum[w].y; }
            g_part[b * 4 + q] = make_float2(a, a2);
        }
    }

    grid_barrier(0);

    // ============ Phase B: stats finalize + xp + router gates (32 CTAs) =====
    if (bid < TOK) {
        const int b = bid;
        if (tid == 0) {
            float s = 0.f, s2 = 0.f;
            #pragma unroll
            for (int q = 0; q < 4; q++) { float2 p = g_part[b * 4 + q]; s += p.x; s2 += p.y; }
            const float mean = s * (1.f / LSEQ);
            const float var  = s2 * (1.f / LSEQ) - mean * mean;
            const float stdv = sqrtf(var + 1e-5f);
            sm.b.mean = mean; sm.b.stdv = stdv;
            g_stats[b * 2] = mean; g_stats[b * 2 + 1] = stdv;
        }
        __syncthreads();
        const float mean = sm.b.mean, inv_std = 1.f / sm.b.stdv;

        if (tid < 64) sm.b.xn[tid] = (g_row64[b * 64 + tid] - mean) * inv_std;
        __syncthreads();

        // xp[p][j]: thread = j, loop p
        {
            const int j = tid;
            float wreg[PLEN];
            #pragma unroll
            for (int k = 0; k < PLEN; k++) wreg[k] = Wp[j * PLEN + k];
            const float bj = bp[j];
            #pragma unroll
            for (int p = 0; p < PTCH; p++) {
                float a = bj;
                #pragma unroll
                for (int k = 0; k < PLEN; k++) a += sm.b.xn[p * PLEN + k] * wreg[k];
                sm.b.xps[p * DDIM + j] = a;
                g_xp[(b * PTCH + p) * DDIM + j] = a;
            }
        }
        __syncthreads();

        // router logits (32 outputs: p x e)
        if (tid < 32) {
            const int p = tid >> 3, e = tid & 7;
            float lg = br[e];
            const float* wr = Wr + e * DDIM;
            const float* xr = sm.b.xps + p * DDIM;
            #pragma unroll 8
            for (int jj = 0; jj < DDIM; jj++) lg += xr[jj] * wr[jj];
            sm.b.lgs[tid] = lg;
        }
        __syncthreads();

        // softmax per patch
        if (tid < PTCH) {
            float mx = -1e30f;
            #pragma unroll
            for (int e = 0; e < NEXP; e++) mx = fmaxf(mx, sm.b.lgs[tid * 8 + e]);
            float ex[NEXP]; float smm = 0.f;
            #pragma unroll
            for (int e = 0; e < NEXP; e++) { ex[e] = expf(sm.b.lgs[tid * 8 + e] - mx); smm += ex[e]; }
            const float inv = 1.f / smm;
            #pragma unroll
            for (int e = 0; e < NEXP; e++) g_gates[(b * PTCH + tid) * NEXP + e] = ex[e] * inv;
        }
    }

    grid_barrier(1);

    // ====== Phase C: gated expert GEMM -> per-expert partials (no atomics) ==
    {
        const int e  = bid >> 4;
        const int h0 = (bid & 15) * 16;
        const int row_base = (warp >> 2) * 64;   // 0 or 64
        const int hl = (warp & 3) * 4;           // local h base: 0,4,8,12

        unsigned long long acc[2][4];
        #pragma unroll
        for (int q = 0; q < 2; q++)
            #pragma unroll
            for (int j = 0; j < 4; j++) acc[q][j] = 0ull;

        const float* Wbase = We + ((size_t)e * DDIM + h0) * DDIM;

        for (int kt = 0; kt < 4; kt++) {
            const int k0 = kt * 64;
            #pragma unroll
            for (int i = 0; i < 8; i++) {
                const int idx = tid + i * 256;
                const int r = idx >> 4, c = (idx & 15) * 4;
                *(float4*)&sm.c.xp[r][c] = *(const float4*)&g_xp[r * DDIM + k0 + c];
            }
            {
                const int r = tid >> 4, c = (tid & 15) * 4;
                *(float4*)&sm.c.w[r][c] = *(const float4*)&Wbase[r * DDIM + k0 + c];
            }
            __syncthreads();

            #pragma unroll
            for (int kk = 0; kk < 64; kk += 4) {
                ulonglong2 xv[2];
                #pragma unroll
                for (int q = 0; q < 2; q++)
                    xv[q] = *(const ulonglong2*)&sm.c.xp[row_base + q * 32 + lane][kk];
                #pragma unroll
                for (int j = 0; j < 4; j++) {
                    const ulonglong2 wv = *(const ulonglong2*)&sm.c.w[hl + j][kk];
                    #pragma unroll
                    for (int q = 0; q < 2; q++) {
                        ffma2(acc[q][j], xv[q].x, wv.x);
                        ffma2(acc[q][j], xv[q].y, wv.y);
                    }
                }
            }
            __syncthreads();
        }

        #pragma unroll
        for (int q = 0; q < 2; q++) {
            const int tp = row_base + q * 32 + lane;
            const float g = g_gates[tp * NEXP + e];
            #pragma unroll
            for (int j = 0; j < 4; j++) {
                const int h = h0 + hl + j;
                const float2 f = *(const float2*)&acc[q][j];
                g_epart[e][tp][h] = g * (f.x + f.y + be[e * DDIM + h]);
            }
        }
    }

    grid_barrier(2);

    // ===== Phase D: e-reduce + head GEMV with denorm folded into epilogue ===
    {
        const int b = bid >> 2, tq = bid & 3;

        // comb[i] = sum_e epart[e][b*4 + i/256][i%256]  (pre-denorm)
        {
            const int i0 = tid * 4;
            const int p = i0 >> 8, h = i0 & 255;
            float4 sum = make_float4(0.f, 0.f, 0.f, 0.f);
            #pragma unroll
            for (int e = 0; e < NEXP; e++) {
                const float4 v = *(const float4*)&g_epart[e][b * 4 + p][h];
                sum.x += v.x; sum.y += v.y; sum.z += v.z; sum.w += v.w;
            }
            *(float4*)&sm.d.comb[i0] = sum;
        }
        __syncthreads();

        const float mean = g_stats[b * 2], stdv = g_stats[b * 2 + 1];

        // out[b][t] = stdv * <comb, Wh[t]> + mean * sum(Wh[t]) + bh[t]
        #pragma unroll
        for (int r = 0; r < 3; r++) {
            const int t = tq * 24 + warp * 3 + r;
            const float* wrow = Wh + (size_t)t * LSEQ;
            float acc = 0.f, ws = 0.f;
            #pragma unroll
            for (int i = 0; i < 8; i++) {
                const float4 w  = *(const float4*)&wrow[lane * 4 + i * 128];
                const float4 cv = *(const float4*)&sm.d.comb[lane * 4 + i * 128];
                acc += w.x * cv.x + w.y * cv.y + w.z * cv.z + w.w * cv.w;
                ws  += w.x + w.y + w.z + w.w;
            }
            #pragma unroll
            for (int o = 16; o > 0; o >>= 1) {
                acc += __shfl_xor_sync(0xffffffffu, acc, o);
                ws  += __shfl_xor_sync(0xffffffffu, ws,  o);
            }
            if (lane == 0) out[b * PRED + t] = stdv * acc + mean * ws + bh[t];
        }
    }
}

// ---------------------------------------------------------------------------
extern "C" void kernel_launch(void* const* d_in, const int* in_sizes, int n_in,
                              void* d_out, int out_size)
{
    const float* x  = (const float*)d_in[0];
    // d_in[1..3]: x_mark_enc, x_dec, x_mark_dec — unused by the reference math
    const float* Wp = (const float*)d_in[4];
    const float* bp = (const float*)d_in[5];
    const float* Wr = (const float*)d_in[6];
    const float* br = (const float*)d_in[7];
    const float* We = (const float*)d_in[8];
    const float* be = (const float*)d_in[9];
    const float* Wh = (const float*)d_in[10];
    const float* bh = (const float*)d_in[11];
    float* out = (float*)d_out;

    fused_kernel<<<GRID, NTHR>>>(x, Wp, bp, Wr, br, We, be, Wh, bh, out);
}

// round 9
// speedup vs baseline: 1.6231x; 1.3672x over previous
#include <cuda_runtime.h>
#include <math.h>
#include <stdint.h>

// Problem constants (fixed shapes)
#define TOK   32      // only channel n=0 of each batch survives the final slice
#define LSEQ  1024
#define CCH   34
#define DDIM  256
#define NEXP  8
#define PTCH  4       // only first 4 patches survive flat[:, :1024]
#define PLEN  16
#define PRED  96
#define GRID  128
#define NTHR  256
#define CLUSTER 4

// Scratch (device globals — no allocation allowed)
__device__ float  g_stats[TOK * 2];                // mean, std per token
__device__ float  g_xp[TOK * PTCH * DDIM];         // 128 x 256
__device__ float  g_gates[TOK * PTCH * NEXP];      // 128 x 8
__device__ float  g_epart[NEXP][TOK * PTCH][DDIM]; // per-expert gated partials (1 MB)
__device__ unsigned g_cnt[2];                      // barrier arrive counters
__device__ unsigned g_gen[2];                      // barrier generations (monotonic)

// ---------------------------------------------------------------------------
// Cluster / DSMEM helpers
// ---------------------------------------------------------------------------
__device__ __forceinline__ uint32_t smem_cvt(const void* p) {
    uint32_t a;
    asm("{ .reg .u64 t; cvta.to.shared.u64 t, %1; cvt.u32.u64 %0, t; }"
        : "=r"(a) : "l"(p));
    return a;
}
__device__ __forceinline__ uint32_t mapa_u32(uint32_t a, uint32_t rank) {
    uint32_t r;
    asm("mapa.shared::cluster.u32 %0, %1, %2;" : "=r"(r) : "r"(a), "r"(rank));
    return r;
}
__device__ __forceinline__ void st_cluster_f2(uint32_t addr, float2 v) {
    unsigned long long u = *(unsigned long long*)&v;
    asm volatile("st.shared::cluster.b64 [%0], %1;" :: "r"(addr), "l"(u) : "memory");
}
__device__ __forceinline__ float ld_cluster_f32(uint32_t addr) {
    float v;
    asm volatile("ld.shared::cluster.f32 %0, [%1];" : "=f"(v) : "r"(addr) : "memory");
    return v;
}
#define CLUSTER_SYNC() do { \
    asm volatile("barrier.cluster.arrive.aligned;" ::: "memory"); \
    asm volatile("barrier.cluster.wait.aligned;"   ::: "memory"); \
} while (0)

// ---------------------------------------------------------------------------
// Grid barrier: all GRID CTAs co-resident; tight L2 spin (no nanosleep).
// Counter self-resets; generation is monotonic across graph replays.
// ---------------------------------------------------------------------------
__device__ __forceinline__ void grid_barrier(int k)
{
    __syncthreads();
    __threadfence();                       // publish prior writes
    if (threadIdx.x == 0) {
        volatile unsigned* genp = &g_gen[k];
        const unsigned g = *genp;
        const unsigned arrived = atomicAdd(&g_cnt[k], 1u) + 1u;
        if (arrived == GRID) {
            g_cnt[k] = 0;
            __threadfence();
            atomicAdd(&g_gen[k], 1u);      // release
        } else {
            while (*genp == g) {}
        }
        __threadfence();                   // acquire
    }
    __syncthreads();
}

__device__ __forceinline__ void ffma2(unsigned long long& acc,
                                      unsigned long long a,
                                      unsigned long long b)
{
    asm("fma.rn.f32x2 %0, %1, %2, %0;" : "+l"(acc) : "l"(a), "l"(b));
}

// Shared memory, phase-overlaid (max ~39.2 KB < 48 KB static limit)
struct SmemAB {
    float  row[256];       // this CTA's raw quarter (rank 0's slice read by B)
    float2 part[CLUSTER];  // gathered quarter (sum, sumsq)
    float2 wsum[8];
    float  xps[DDIM];      // xp for this tp row
    float  lgs[NEXP];
    float  xn[PLEN];
    float  mean, stdv;
};
struct SmemC { float xp[128][68]; float w[16][68]; };  // stride 68: conflict-free 16B LDS
struct SmemD { float comb[LSEQ]; };

__global__ void __launch_bounds__(NTHR, 1) __cluster_dims__(CLUSTER, 1, 1)
fused_kernel(const float* __restrict__ x,
             const float* __restrict__ Wp, const float* __restrict__ bp,
             const float* __restrict__ Wr, const float* __restrict__ br,
             const float* __restrict__ We, const float* __restrict__ be,
             const float* __restrict__ Wh, const float* __restrict__ bh,
             float* __restrict__ out)
{
    __shared__ union { SmemAB ab; SmemC c; SmemD d; } sm;

    const int bid = blockIdx.x;
    const int tid = threadIdx.x, lane = tid & 31, warp = tid >> 5;

    // ---- L2 prefetch of ALL later-phase weights (overlaps phase A) --------
    {
        // We: 2MB / 128 CTAs = 128 lines of 128B each
        const char* wp = (const char*)(We + (size_t)bid * 4096);
        if (tid < 128)
            asm volatile("prefetch.global.L2 [%0];" :: "l"(wp + tid * 128));
        // Wh: 384KB / 128 CTAs = 24 lines
        const char* hp = (const char*)(Wh + (size_t)bid * 768);
        if (tid < 24)
            asm volatile("prefetch.global.L2 [%0];" :: "l"(hp + tid * 128));
        if (tid == 0) {
            // Wp: 16KB = 128 lines (one per CTA)
            asm volatile("prefetch.global.L2 [%0];" :: "l"((const char*)Wp + bid * 128));
            if (bid < 64) {  // Wr: 8KB, be: 8KB
                asm volatile("prefetch.global.L2 [%0];" :: "l"((const char*)Wr + bid * 128));
                asm volatile("prefetch.global.L2 [%0];" :: "l"((const char*)be + bid * 128));
            }
            if (bid < 8)     // bp: 1KB
                asm volatile("prefetch.global.L2 [%0];" :: "l"((const char*)bp + bid * 128));
            if (bid < 3)     // bh: 384B
                asm volatile("prefetch.global.L2 [%0];" :: "l"((const char*)bh + bid * 128));
        }
    }

    // ================= Phase A: gather quarter + partial stats =============
    // CTA = (token b, quarter q). Cluster of 4 CTAs = one token.
    {
        const int b = bid >> 2, q = bid & 3;
        const float v = x[((size_t)(b * LSEQ + q * 256 + tid)) * CCH + 2];
        sm.ab.row[tid] = v;

        float s = v, s2 = v * v;
        #pragma unroll
        for (int o = 16; o > 0; o >>= 1) {
            s  += __shfl_down_sync(0xffffffffu, s,  o);
            s2 += __shfl_down_sync(0xffffffffu, s2, o);
        }
        if (lane == 0) sm.ab.wsum[warp] = make_float2(s, s2);
        __syncthreads();
        if (tid == 0) {
            float a = 0.f, a2 = 0.f;
            #pragma unroll
            for (int w = 0; w < 8; w++) { a += sm.ab.wsum[w].x; a2 += sm.ab.wsum[w].y; }
            // scatter this quarter's partial to all 4 cluster CTAs via DSMEM
            const uint32_t la = smem_cvt(&sm.ab.part[q]);
            #pragma unroll
            for (int r = 0; r < CLUSTER; r++)
                st_cluster_f2(mapa_u32(la, r), make_float2(a, a2));
        }
    }
    CLUSTER_SYNC();   // orders DSMEM partials + row[] across the token's 4 CTAs

    // ===== Phase B: stats finalize + xp + router gates (FULL width) ========
    // CTA = (token b, patch p). p == q from phase A.
    {
        const int b = bid >> 2, p = bid & 3;
        const int tp = b * PTCH + p;

        if (tid == 0) {
            float s = 0.f, s2 = 0.f;
            #pragma unroll
            for (int q = 0; q < CLUSTER; q++) { float2 pp = sm.ab.part[q]; s += pp.x; s2 += pp.y; }
            const float mean = s * (1.f / LSEQ);
            const float var  = s2 * (1.f / LSEQ) - mean * mean;
            const float stdv = sqrtf(var + 1e-5f);
            sm.ab.mean = mean; sm.ab.stdv = stdv;
            if (p == 0) { g_stats[b * 2] = mean; g_stats[b * 2 + 1] = stdv; }
        }
        __syncthreads();
        const float mean = sm.ab.mean, inv_std = 1.f / sm.ab.stdv;

        // normalized patch samples live in rank 0's row[p*16 .. p*16+15]
        if (tid < PLEN) {
            const uint32_t la = smem_cvt(&sm.ab.row[p * PLEN + tid]);
            const float v = ld_cluster_f32(mapa_u32(la, 0));
            sm.ab.xn[tid] = (v - mean) * inv_std;
        }
        __syncthreads();

        // xp[j] = xn . Wp[j] + bp[j], thread = j
        {
            const int j = tid;
            float wreg[PLEN];
            #pragma unroll
            for (int k = 0; k < PLEN; k++) wreg[k] = Wp[j * PLEN + k];
            float a = bp[j];
            #pragma unroll
            for (int k = 0; k < PLEN; k++) a += sm.ab.xn[k] * wreg[k];
            sm.ab.xps[j] = a;
            g_xp[tp * DDIM + j] = a;
        }
        __syncthreads();

        // router logits: warp e, shuffle reduce over 256 elements
        {
            const int e = warp;
            const float* wr = Wr + e * DDIM + lane * 8;
            const float4 w0 = *(const float4*)wr;
            const float4 w1 = *(const float4*)(wr + 4);
            const float4 x0 = *(const float4*)&sm.ab.xps[lane * 8];
            const float4 x1 = *(const float4*)&sm.ab.xps[lane * 8 + 4];
            float lg = w0.x * x0.x + w0.y * x0.y + w0.z * x0.z + w0.w * x0.w
                     + w1.x * x1.x + w1.y * x1.y + w1.z * x1.z + w1.w * x1.w;
            #pragma unroll
            for (int o = 16; o > 0; o >>= 1) lg += __shfl_xor_sync(0xffffffffu, lg, o);
            if (lane == 0) sm.ab.lgs[e] = lg + br[e];
        }
        __syncthreads();

        // softmax -> gates
        if (tid == 0) {
            float mx = -1e30f;
            #pragma unroll
            for (int e = 0; e < NEXP; e++) mx = fmaxf(mx, sm.ab.lgs[e]);
            float ex[NEXP]; float smm = 0.f;
            #pragma unroll
            for (int e = 0; e < NEXP; e++) { ex[e] = expf(sm.ab.lgs[e] - mx); smm += ex[e]; }
            const float inv = 1.f / smm;
            #pragma unroll
            for (int e = 0; e < NEXP; e++) g_gates[tp * NEXP + e] = ex[e] * inv;
        }
    }

    grid_barrier(0);

    // ====== Phase C: gated expert GEMM -> per-expert partials (no atomics) ==
    {
        const int e  = bid >> 4;
        const int h0 = (bid & 15) * 16;
        const int row_base = (warp >> 2) * 64;   // 0 or 64
        const int hl = (warp & 3) * 4;           // local h base: 0,4,8,12

        unsigned long long acc[2][4];
        #pragma unroll
        for (int q = 0; q < 2; q++)
            #pragma unroll
            for (int j = 0; j < 4; j++) acc[q][j] = 0ull;

        const float* Wbase = We + ((size_t)e * DDIM + h0) * DDIM;

        for (int kt = 0; kt < 4; kt++) {
            const int k0 = kt * 64;
            #pragma unroll
            for (int i = 0; i < 8; i++) {
                const int idx = tid + i * 256;
                const int r = idx >> 4, c = (idx & 15) * 4;
                *(float4*)&sm.c.xp[r][c] = *(const float4*)&g_xp[r * DDIM + k0 + c];
            }
            {
                const int r = tid >> 4, c = (tid & 15) * 4;
                *(float4*)&sm.c.w[r][c] = *(const float4*)&Wbase[r * DDIM + k0 + c];
            }
            __syncthreads();

            #pragma unroll
            for (int kk = 0; kk < 64; kk += 4) {
                ulonglong2 xv[2];
                #pragma unroll
                for (int q = 0; q < 2; q++)
                    xv[q] = *(const ulonglong2*)&sm.c.xp[row_base + q * 32 + lane][kk];
                #pragma unroll
                for (int j = 0; j < 4; j++) {
                    const ulonglong2 wv = *(const ulonglong2*)&sm.c.w[hl + j][kk];
                    #pragma unroll
                    for (int q = 0; q < 2; q++) {
                        ffma2(acc[q][j], xv[q].x, wv.x);
                        ffma2(acc[q][j], xv[q].y, wv.y);
                    }
                }
            }
            __syncthreads();
        }

        #pragma unroll
        for (int q = 0; q < 2; q++) {
            const int tp = row_base + q * 32 + lane;
            const float g = g_gates[tp * NEXP + e];
            #pragma unroll
            for (int j = 0; j < 4; j++) {
                const int h = h0 + hl + j;
                const float2 f = *(const float2*)&acc[q][j];
                g_epart[e][tp][h] = g * (f.x + f.y + be[e * DDIM + h]);
            }
        }
    }

    grid_barrier(1);

    // ===== Phase D: e-reduce + head GEMV with denorm folded into epilogue ===
    {
        const int b = bid >> 2, tq = bid & 3;

        // comb[i] = sum_e epart[e][b*4 + i/256][i%256]  (pre-denorm)
        {
            const int i0 = tid * 4;
            const int p = i0 >> 8, h = i0 & 255;
            float4 sum = make_float4(0.f, 0.f, 0.f, 0.f);
            #pragma unroll
            for (int e = 0; e < NEXP; e++) {
                const float4 v = *(const float4*)&g_epart[e][b * 4 + p][h];
                sum.x += v.x; sum.y += v.y; sum.z += v.z; sum.w += v.w;
            }
            *(float4*)&sm.d.comb[i0] = sum;
        }
        __syncthreads();

        const float mean = g_stats[b * 2], stdv = g_stats[b * 2 + 1];

        // out[b][t] = stdv * <comb, Wh[t]> + mean * sum(Wh[t]) + bh[t]
        #pragma unroll
        for (int r = 0; r < 3; r++) {
            const int t = tq * 24 + warp * 3 + r;
            const float* wrow = Wh + (size_t)t * LSEQ;
            float acc = 0.f, ws = 0.f;
            #pragma unroll
            for (int i = 0; i < 8; i++) {
                const float4 w  = *(const float4*)&wrow[lane * 4 + i * 128];
                const float4 cv = *(const float4*)&sm.d.comb[lane * 4 + i * 128];
                acc += w.x * cv.x + w.y * cv.y + w.z * cv.z + w.w * cv.w;
                ws  += w.x + w.y + w.z + w.w;
            }
            #pragma unroll
            for (int o = 16; o > 0; o >>= 1) {
                acc += __shfl_xor_sync(0xffffffffu, acc, o);
                ws  += __shfl_xor_sync(0xffffffffu, ws,  o);
            }
            if (lane == 0) out[b * PRED + t] = stdv * acc + mean * ws + bh[t];
        }
    }
}

// ---------------------------------------------------------------------------
extern "C" void kernel_launch(void* const* d_in, const int* in_sizes, int n_in,
                              void* d_out, int out_size)
{
    const float* x  = (const float*)d_in[0];
    // d_in[1..3]: x_mark_enc, x_dec, x_mark_dec — unused by the reference math
    const float* Wp = (const float*)d_in[4];
    const float* bp = (const float*)d_in[5];
    const float* Wr = (const float*)d_in[6];
    const float* br = (const float*)d_in[7];
    const float* We = (const float*)d_in[8];
    const float* be = (const float*)d_in[9];
    const float* Wh = (const float*)d_in[10];
    const float* bh = (const float*)d_in[11];
    float* out = (float*)d_out;

    fused_kernel<<<GRID, NTHR>>>(x, Wp, bp, Wr, br, We, be, Wh, bh, out);
}